// round 9
// baseline (speedup 1.0000x reference)
#include <cuda_runtime.h>
#include <cuda_fp16.h>
#include <cstdint>

// ---------------- problem constants ----------------
#define K_DIM   256
#define N_DIM   256
#define M_CTA   64
#define N_CTA   128
#define THREADS 256           // 8 warps: 2 (M) x 4 (N), warp tile 32x32

#define K_CHUNK 32            // fp32 A chunk (128 B per row)
#define N_CHUNKS 8
#define RING     4

// smem layout (bytes) -- unpadded, XOR-swizzled tiles
#define OFF_SCALE 0                            // 128 f32
#define OFF_BIAS  512                          // 128 f32
#define OFF_A     1024
#define CH_BYTES  (64 * 128)                   // 8192 per stage
#define OFF_B     (OFF_A + RING * CH_BYTES)    // 33792
#define B_BYTES   (128 * 512)                  // 65536
#define SMEM_TOTAL (OFF_B + B_BYTES)           // 99328 -> 2 CTAs/SM

__device__ __forceinline__ uint32_t smem_u32(const void* p) {
    uint32_t a;
    asm("{ .reg .u64 t; cvta.to.shared.u64 t, %1; cvt.u32.u64 %0, t; }"
        : "=r"(a) : "l"(p));
    return a;
}
__device__ __forceinline__ void cp16(uint32_t dst, const void* src) {
    asm volatile("cp.async.cg.shared.global [%0], [%1], 16;" :: "r"(dst), "l"(src) : "memory");
}
#define CP_COMMIT() asm volatile("cp.async.commit_group;" ::: "memory")
#define CP_WAIT(n)  asm volatile("cp.async.wait_group %0;" :: "n"(n) : "memory")

__device__ __forceinline__ void ldsm4(uint32_t& r0, uint32_t& r1, uint32_t& r2, uint32_t& r3,
                                      uint32_t addr) {
    asm volatile("ldmatrix.sync.aligned.m8n8.x4.shared.b16 {%0,%1,%2,%3}, [%4];"
                 : "=r"(r0), "=r"(r1), "=r"(r2), "=r"(r3) : "r"(addr));
}
__device__ __forceinline__ void lds64(float& a, float& b, uint32_t addr) {
    asm volatile("ld.shared.v2.f32 {%0,%1}, [%2];" : "=f"(a), "=f"(b) : "r"(addr));
}
__device__ __forceinline__ void mma16816(float* c, const uint32_t* a, uint32_t b0, uint32_t b1) {
    asm volatile(
        "mma.sync.aligned.m16n8k16.row.col.f32.f16.f16.f32 "
        "{%0,%1,%2,%3}, {%4,%5,%6,%7}, {%8,%9}, {%0,%1,%2,%3};"
        : "+f"(c[0]), "+f"(c[1]), "+f"(c[2]), "+f"(c[3])
        : "r"(a[0]), "r"(a[1]), "r"(a[2]), "r"(a[3]), "r"(b0), "r"(b1));
}
__device__ __forceinline__ uint32_t pack2(float lo, float hi) {
    __half2 h = __floats2half2_rn(lo, hi);
    return *(uint32_t*)&h;
}

// Binarized weight sign(W) as fp16 (+-1 exact), prepared per launch.
__device__ __align__(16) __half g_bsign[N_DIM * K_DIM];

__global__ void prep_bsign(const float* __restrict__ W) {
    int i = blockIdx.x * blockDim.x + threadIdx.x;
    if (i < N_DIM * K_DIM) {
        float w = W[i];
        g_bsign[i] = __float2half((w > 0.f) ? 1.f : ((w < 0.f) ? -1.f : 0.f));
    }
}

__global__ __launch_bounds__(THREADS, 2)
void binlin_gemm(const float* __restrict__ x,
                 const float* __restrict__ scale,
                 const float* __restrict__ bias,
                 float* __restrict__ out) {
    extern __shared__ char smem[];
    float* sScale = (float*)(smem + OFF_SCALE);
    float* sBias  = (float*)(smem + OFF_BIAS);
    const uint32_t sAu = smem_u32(smem + OFF_A);
    const uint32_t sBu = smem_u32(smem + OFF_B);

    const int tid  = threadIdx.x;
    const int wid  = tid >> 5;
    const int lane = tid & 31;
    const int wm   = wid & 1;        // 0..1 (M, 32 rows each)
    const int wn   = wid >> 1;       // 0..3 (N, 32 cols each)
    const int g    = lane >> 2;      // 0..7
    const int t    = lane & 3;       // 0..3

    const int mblk = blockIdx.x >> 1;
    const int nblk = blockIdx.x & 1;
    const int m_base = mblk * M_CTA;
    const int n_base = nblk * N_CTA;

    const float* xbase = x + (size_t)m_base * K_DIM;

    // ---- scale/bias for this N block ----
    if (tid < 128) {
        sScale[tid] = scale[n_base + tid];
        sBias[tid]  = bias[n_base + tid];
    }

    // A chunk loader: 512 x 16B items, 2 per thread. row stride 128 B, swizzled.
    auto issue_chunk = [&](int c) {
        const uint32_t buf = sAu + (uint32_t)(c & (RING - 1)) * CH_BYTES;
        const float* src = xbase + c * K_CHUNK;
        #pragma unroll
        for (int it = 0; it < 2; it++) {
            const int item = tid + it * THREADS;     // 0..511
            const int r = item >> 3;
            const int q = item & 7;
            cp16(buf + r * 128 + 16 * (q ^ (r & 7)),
                 src + (size_t)r * K_DIM + q * 4);
        }
    };

    // ---- prologue: B (+chunk0) group0, chunk1 g1, chunk2 g2 ----
    {
        const __half* bsrc = g_bsign + (size_t)n_base * K_DIM;
        #pragma unroll
        for (int i = 0; i < 16; i++) {
            int c   = tid + THREADS * i;        // 0..4095
            int r   = c >> 5;                   // row 0..127
            int q   = c & 31;                   // 16B chunk in row
            cp16(sBu + r * 512 + 16 * (q ^ (r & 7)), bsrc + r * K_DIM + q * 8);
        }
    }
    issue_chunk(0); CP_COMMIT();
    issue_chunk(1); CP_COMMIT();
    issue_chunk(2); CP_COMMIT();

    // ---- B ldmatrix addressing (swizzled): row, 16B chunk = 2*ks + (lane>>4) ----
    const int brow  = wn * 32 + (lane & 15);
    const uint32_t bRowBase = sBu + brow * 512;
    const int bqx   = (lane >> 4);              // 0 or 1 (k-half)
    const int bswz  = brow & 7;

    // A fragment addressing (swizzled fp32 rows, 128 B)
    const int ar0 = wm * 32 + g;                 // tile i=0 row g
    // rows: ar0, ar0+8 (tile0), ar0+16, ar0+24 (tile1)

    float acc[2][4][4];
    #pragma unroll
    for (int i = 0; i < 2; i++)
        #pragma unroll
        for (int j = 0; j < 4; j++)
            #pragma unroll
            for (int e = 0; e < 4; e++)
                acc[i][j][e] = 0.f;

    uint32_t bfr[2][2][4];   // [buf][n16 group][4]

    // helper: load B frags for k16 index ks into buffer bb
    auto loadB = [&](int bb, int ks) {
        const int q = 2 * ks + bqx;
        #pragma unroll
        for (int p = 0; p < 2; p++) {
            const int r = brow + p * 16;                 // p row group (n16 tiles 0,1)
            const uint32_t addr = sBu + (uint32_t)r * 512 + 16 * (q ^ (r & 7));
            ldsm4(bfr[bb][p][0], bfr[bb][p][1], bfr[bb][p][2], bfr[bb][p][3], addr);
        }
    };

    // helper: build A frags for (chunk buffer, step)
    auto buildA = [&](uint32_t abuf, int step, uint32_t afr[2][4]) {
        #pragma unroll
        for (int i = 0; i < 2; i++) {
            #pragma unroll
            for (int hk = 0; hk < 2; hk++) {
                // rows ar0+i*16 (lo regs 0/2... reg = hk*2 + rowgrp)
                const int q  = 4 * step + 2 * hk + (t >> 1);
                const int ob = 8 * (t & 1);
                const int rA = ar0 + i * 16;
                const int rB = rA + 8;
                float a0, a1, b0, b1;
                lds64(a0, a1, sAu + (abuf - sAu) + rA * 128 + 16 * (q ^ (rA & 7)) + ob);
                lds64(b0, b1, sAu + (abuf - sAu) + rB * 128 + 16 * (q ^ (rB & 7)) + ob);
                afr[i][hk * 2 + 0] = pack2(a0, a1);
                afr[i][hk * 2 + 1] = pack2(b0, b1);
            }
        }
    };

    // ---- first chunk ready ----
    CP_WAIT(2);
    __syncthreads();
    loadB(0, 0);

    // ---- chunk loop ----
    #pragma unroll
    for (int c = 0; c < N_CHUNKS; c++) {
        const uint32_t abuf = sAu + (uint32_t)(c & (RING - 1)) * CH_BYTES;

        #pragma unroll
        for (int step = 0; step < 2; step++) {
            const int ks  = 2 * c + step;
            const int cur = ks & 1;

            uint32_t afr[2][4];
            buildA(abuf, step, afr);

            if (ks < 15) loadB(cur ^ 1, ks + 1);    // prefetch next-step B frags

            #pragma unroll
            for (int i = 0; i < 2; i++)
                #pragma unroll
                for (int j = 0; j < 4; j++) {
                    const int p = j >> 1, h = j & 1;
                    mma16816(acc[i][j], afr[i], bfr[cur][p][h], bfr[cur][p][h + 2]);
                }
        }

        if (c + 3 < N_CHUNKS) { issue_chunk(c + 3); CP_COMMIT(); }

        if (c < N_CHUNKS - 1) {
            if (c < 5)       { CP_WAIT(2); }
            else if (c == 5) { CP_WAIT(1); }
            else             { CP_WAIT(0); }
            __syncthreads();
        }
    }

    // ---- register epilogue: scale*acc + bias, direct STG ----
    #pragma unroll
    for (int i = 0; i < 2; i++) {
        const int r0 = m_base + wm * 32 + i * 16 + g;
        float* dst0 = out + (size_t)r0 * N_DIM + n_base + wn * 32;
        float* dst1 = dst0 + 8 * N_DIM;
        #pragma unroll
        for (int j = 0; j < 4; j++) {
            const int col = j * 8 + 2 * t;
            const float2 sc = *(const float2*)(sScale + wn * 32 + col);
            const float2 bi = *(const float2*)(sBias  + wn * 32 + col);
            float2 v0, v1;
            v0.x = acc[i][j][0] * sc.x + bi.x;
            v0.y = acc[i][j][1] * sc.y + bi.y;
            v1.x = acc[i][j][2] * sc.x + bi.x;
            v1.y = acc[i][j][3] * sc.y + bi.y;
            *(float2*)(dst0 + col) = v0;
            *(float2*)(dst1 + col) = v1;
        }
    }
}

extern "C" void kernel_launch(void* const* d_in, const int* in_sizes, int n_in,
                              void* d_out, int out_size) {
    const float* x     = (const float*)d_in[0];
    const float* W     = (const float*)d_in[1];
    const float* scale = (const float*)d_in[2];
    const float* bias  = (const float*)d_in[3];
    float* out = (float*)d_out;

    const int M = in_sizes[0] / K_DIM;              // 131072
    const int grid = (M / M_CTA) * 2;               // 4096

    prep_bsign<<<(N_DIM * K_DIM + 255) / 256, 256>>>(W);

    cudaFuncSetAttribute(binlin_gemm, cudaFuncAttributeMaxDynamicSharedMemorySize, SMEM_TOTAL);
    binlin_gemm<<<grid, THREADS, SMEM_TOTAL>>>(x, scale, bias, out);
}

// round 10
// speedup vs baseline: 1.1525x; 1.1525x over previous
#include <cuda_runtime.h>
#include <cuda_fp16.h>
#include <cstdint>

// ---------------- problem constants ----------------
#define K_DIM   256
#define N_DIM   256
#define M_CTA   64
#define N_CTA   128
#define THREADS 128           // 4 warps: 2 (M) x 2 (N), warp tile 32x64

// smem layout (bytes) -- unpadded, XOR-swizzled fp16 tiles (512 B rows)
#define OFF_SCALE 0                           // 128 f32
#define OFF_BIAS  512                         // 128 f32
#define OFF_A     1024
#define A_BYTES   (64 * 512)                  // 32768
#define OFF_B     (OFF_A + A_BYTES)           // 33792
#define B_BYTES   (128 * 512)                 // 65536
#define SMEM_TOTAL (OFF_B + B_BYTES)          // 99328 -> 2 CTAs/SM

__device__ __forceinline__ uint32_t smem_u32(const void* p) {
    uint32_t a;
    asm("{ .reg .u64 t; cvta.to.shared.u64 t, %1; cvt.u32.u64 %0, t; }"
        : "=r"(a) : "l"(p));
    return a;
}
__device__ __forceinline__ void cp16(uint32_t dst, const void* src) {
    asm volatile("cp.async.cg.shared.global [%0], [%1], 16;" :: "r"(dst), "l"(src) : "memory");
}
#define CP_COMMIT() asm volatile("cp.async.commit_group;" ::: "memory")
#define CP_WAIT0()  asm volatile("cp.async.wait_group 0;" ::: "memory")

__device__ __forceinline__ void ldsm4(uint32_t& r0, uint32_t& r1, uint32_t& r2, uint32_t& r3,
                                      uint32_t addr) {
    asm volatile("ldmatrix.sync.aligned.m8n8.x4.shared.b16 {%0,%1,%2,%3}, [%4];"
                 : "=r"(r0), "=r"(r1), "=r"(r2), "=r"(r3) : "r"(addr));
}
__device__ __forceinline__ void mma16816(float* c, const uint32_t* a, uint32_t b0, uint32_t b1) {
    asm volatile(
        "mma.sync.aligned.m16n8k16.row.col.f32.f16.f16.f32 "
        "{%0,%1,%2,%3}, {%4,%5,%6,%7}, {%8,%9}, {%0,%1,%2,%3};"
        : "+f"(c[0]), "+f"(c[1]), "+f"(c[2]), "+f"(c[3])
        : "r"(a[0]), "r"(a[1]), "r"(a[2]), "r"(a[3]), "r"(b0), "r"(b1));
}

// Binarized weight sign(W) as fp16 (+-1 exact), prepared per launch.
__device__ __align__(16) __half g_bsign[N_DIM * K_DIM];

__global__ void prep_bsign(const float* __restrict__ W) {
    int i = blockIdx.x * blockDim.x + threadIdx.x;
    if (i < N_DIM * K_DIM) {
        float w = W[i];
        g_bsign[i] = __float2half((w > 0.f) ? 1.f : ((w < 0.f) ? -1.f : 0.f));
    }
}

__global__ __launch_bounds__(THREADS, 2)
void binlin_gemm(const float* __restrict__ x,
                 const float* __restrict__ scale,
                 const float* __restrict__ bias,
                 float* __restrict__ out) {
    extern __shared__ char smem[];
    float* sScale = (float*)(smem + OFF_SCALE);
    float* sBias  = (float*)(smem + OFF_BIAS);
    __half* sA    = (__half*)(smem + OFF_A);
    const uint32_t sAu = smem_u32(smem + OFF_A);
    const uint32_t sBu = smem_u32(smem + OFF_B);

    const int tid  = threadIdx.x;
    const int wid  = tid >> 5;
    const int lane = tid & 31;
    const int wm   = wid & 1;        // 0..1 (M, 32 rows each)
    const int wn   = wid >> 1;       // 0..1 (N, 64 cols each)
    const int g    = lane >> 2;      // 0..7
    const int t    = lane & 3;       // 0..3

    const int mblk = blockIdx.x >> 1;
    const int nblk = blockIdx.x & 1;
    const int m_base = mblk * M_CTA;
    const int n_base = nblk * N_CTA;

    // ---- scale/bias for this N block ----
    sScale[tid] = scale[n_base + tid];
    sBias[tid]  = bias[n_base + tid];

    // ---- B tile via cp.async first (overlaps with A LDG below) ----
    // 128 rows x 32 chunks(16B) = 4096 items, 32/thread; swizzled q^(r&7)
    {
        const __half* bsrc = g_bsign + (size_t)n_base * K_DIM;
        #pragma unroll
        for (int i = 0; i < 32; i++) {
            int c = tid + THREADS * i;          // 0..4095
            int r = c >> 5;
            int q = c & 31;
            cp16(sBu + r * 512 + 16 * (q ^ (r & 7)), bsrc + r * K_DIM + q * 8);
        }
    }
    CP_COMMIT();

    // ---- A tile: LDG fp32 -> cvt -> STS.128 fp16, swizzled ----
    // 64 rows x 32 dst-chunks(16B = 8 halves = 2 float4) = 2048 items, 16/thread
    const float* xbase = x + (size_t)m_base * K_DIM;
    #pragma unroll
    for (int i = 0; i < 16; i++) {
        int c  = tid + THREADS * i;             // 0..2047
        int r  = c >> 5;                        // row 0..63
        int cq = c & 31;                        // 16B dst chunk in row
        const float* src = xbase + (size_t)r * K_DIM + cq * 8;
        float4 v0 = *(const float4*)(src);
        float4 v1 = *(const float4*)(src + 4);
        __half2 h0 = __floats2half2_rn(v0.x, v0.y);
        __half2 h1 = __floats2half2_rn(v0.z, v0.w);
        __half2 h2 = __floats2half2_rn(v1.x, v1.y);
        __half2 h3 = __floats2half2_rn(v1.z, v1.w);
        uint4 u;
        u.x = *(uint32_t*)&h0; u.y = *(uint32_t*)&h1;
        u.z = *(uint32_t*)&h2; u.w = *(uint32_t*)&h3;
        *(uint4*)((char*)sA + r * 512 + 16 * (cq ^ (r & 7))) = u;
    }

    CP_WAIT0();
    __syncthreads();

    // ---- fragment addressing (swizzled, 512 B rows) ----
    // A m16 tile i: row = wm*32 + i*16 + (lane&15), chunk q = 2*ks + (lane>>4)
    // B n16 group p: row = wn*64 + p*16 + (lane&15), same q
    const int arow = wm * 32 + (lane & 15);
    const int brow = wn * 64 + (lane & 15);
    const int kq   = lane >> 4;                 // 0/1

    float acc[2][8][4];
    #pragma unroll
    for (int i = 0; i < 2; i++)
        #pragma unroll
        for (int j = 0; j < 8; j++)
            #pragma unroll
            for (int e = 0; e < 4; e++)
                acc[i][j][e] = 0.f;

    uint32_t afr[2][2][4];     // [buf][mtile][4]
    uint32_t bfr[2][4][4];     // [buf][n16 group][4]

    auto loadFrags = [&](int bb, int ks) {
        const int q = 2 * ks + kq;
        #pragma unroll
        for (int i = 0; i < 2; i++) {
            const int r = arow + i * 16;
            ldsm4(afr[bb][i][0], afr[bb][i][1], afr[bb][i][2], afr[bb][i][3],
                  sAu + r * 512 + 16 * (q ^ (r & 7)));
        }
        #pragma unroll
        for (int p = 0; p < 4; p++) {
            const int r = brow + p * 16;
            ldsm4(bfr[bb][p][0], bfr[bb][p][1], bfr[bb][p][2], bfr[bb][p][3],
                  sBu + r * 512 + 16 * (q ^ (r & 7)));
        }
    };

    loadFrags(0, 0);

    // ---- mainloop: 16 k-steps, no barriers, dbl-buffered fragments ----
    #pragma unroll
    for (int ks = 0; ks < 16; ks++) {
        const int cur = ks & 1;
        if (ks < 15) loadFrags(cur ^ 1, ks + 1);
        #pragma unroll
        for (int i = 0; i < 2; i++)
            #pragma unroll
            for (int j = 0; j < 8; j++) {
                const int p = j >> 1, h = j & 1;
                mma16816(acc[i][j], afr[cur][i], bfr[cur][p][h], bfr[cur][p][h + 2]);
            }
    }

    // ---- register epilogue: scale*acc + bias, direct STG ----
    #pragma unroll
    for (int i = 0; i < 2; i++) {
        const int r0 = m_base + wm * 32 + i * 16 + g;
        float* dst0 = out + (size_t)r0 * N_DIM + n_base + wn * 64;
        float* dst1 = dst0 + 8 * N_DIM;
        #pragma unroll
        for (int j = 0; j < 8; j++) {
            const int col = j * 8 + 2 * t;
            const float2 sc = *(const float2*)(sScale + wn * 64 + col);
            const float2 bi = *(const float2*)(sBias  + wn * 64 + col);
            float2 v0, v1;
            v0.x = acc[i][j][0] * sc.x + bi.x;
            v0.y = acc[i][j][1] * sc.y + bi.y;
            v1.x = acc[i][j][2] * sc.x + bi.x;
            v1.y = acc[i][j][3] * sc.y + bi.y;
            *(float2*)(dst0 + col) = v0;
            *(float2*)(dst1 + col) = v1;
        }
    }
}

extern "C" void kernel_launch(void* const* d_in, const int* in_sizes, int n_in,
                              void* d_out, int out_size) {
    const float* x     = (const float*)d_in[0];
    const float* W     = (const float*)d_in[1];
    const float* scale = (const float*)d_in[2];
    const float* bias  = (const float*)d_in[3];
    float* out = (float*)d_out;

    const int M = in_sizes[0] / K_DIM;              // 131072
    const int grid = (M / M_CTA) * 2;               // 4096

    prep_bsign<<<(N_DIM * K_DIM + 255) / 256, 256>>>(W);

    cudaFuncSetAttribute(binlin_gemm, cudaFuncAttributeMaxDynamicSharedMemorySize, SMEM_TOTAL);
    binlin_gemm<<<grid, THREADS, SMEM_TOTAL>>>(x, scale, bias, out);
}